// round 9
// baseline (speedup 1.0000x reference)
#include <cuda_runtime.h>
#include <cuda_bf16.h>

// SAConv: B=4, C=G=COUT=64, D=1, H=W=56, K=7, PAD=3, RDIM=256.
//   q = x*wq; logit_t = (q+u)*wk*xw_t + (q+v)*ro_t,  ro_t = sum_c Wr[g,c]*r[g*4+c,t]
//   out = wv * sum_t softmax(logit)_t * xw_t   (no max-subtraction; |logit| small)
// Each thread computes 7 consecutive rows of one column; window values are
// reused across pixels via registers (sliding window), halving MIO/LDS traffic.
// Packed f32x2 FMA on pixel-pairs (they share ro_t).

#define KW    7
#define PADX  3
#define HH    56
#define WW    56
#define TH    28          // output rows per block tile -> grid = 2 x 256 = 512 (single wave)
#define PW    62          // padded width 56+6
#define SROWS (TH + 6)    // 34 padded rows staged
#define NT    224         // 56 cols x 4 row-groups; 7 consecutive pixels per thread
#define LOG2E 1.4426950408889634f

typedef unsigned long long u64;

__device__ __forceinline__ float ex2a(float x) {
    float y; asm("ex2.approx.ftz.f32 %0, %1;" : "=f"(y) : "f"(x)); return y;
}
__device__ __forceinline__ float rcpa(float x) {
    float y; asm("rcp.approx.ftz.f32 %0, %1;" : "=f"(y) : "f"(x)); return y;
}
__device__ __forceinline__ u64 pack2(float lo, float hi) {
    u64 r; asm("mov.b64 %0, {%1, %2};" : "=l"(r) : "f"(lo), "f"(hi)); return r;
}
__device__ __forceinline__ void unpack2(float& lo, float& hi, u64 v) {
    asm("mov.b64 {%0, %1}, %2;" : "=f"(lo), "=f"(hi) : "l"(v));
}
__device__ __forceinline__ u64 mul2(u64 a, u64 b) {
    u64 r; asm("mul.rn.f32x2 %0, %1, %2;" : "=l"(r) : "l"(a), "l"(b)); return r;
}
__device__ __forceinline__ u64 add2(u64 a, u64 b) {
    u64 r; asm("add.rn.f32x2 %0, %1, %2;" : "=l"(r) : "l"(a), "l"(b)); return r;
}
__device__ __forceinline__ u64 fma2(u64 a, u64 b, u64 c) {
    u64 r; asm("fma.rn.f32x2 %0, %1, %2, %3;" : "=l"(r) : "l"(a), "l"(b), "l"(c)); return r;
}

__global__ __launch_bounds__(NT, 4)
void saconv_kernel(const float* __restrict__ x,  const float* __restrict__ r,
                   const float* __restrict__ Wq, const float* __restrict__ Wk,
                   const float* __restrict__ Wv, const float* __restrict__ Wr,
                   const float* __restrict__ up, const float* __restrict__ vp,
                   float* __restrict__ out)
{
    __shared__ float sp[SROWS * PW];
    __shared__ float ros[52];

    const int tile  = blockIdx.x;        // 0..1 (row tiles)
    const int plane = blockIdx.y;        // 0..255 = b*64 + g
    const int g     = plane & 63;
    const int tid   = threadIdx.x;
    const int h0    = tile * TH;

    // Stage padded plane slice: padded rows [h0, h0+SROWS).
    const float* xp = x + (size_t)plane * HH * WW;
    for (int idx = tid; idx < SROWS * PW; idx += NT) {
        int pr = idx / PW, pc = idx - pr * PW;
        int gh = h0 + pr - PADX;
        int gw = pc - PADX;
        float vv = 0.0f;
        if ((unsigned)gh < HH && (unsigned)gw < WW) vv = xp[gh * WW + gw];
        sp[idx] = vv;
    }

    // ro[t] = sum_c Wr[g,0,c] * r[g*4+c, t]
    if (tid < 49) {
        float s = 0.0f;
        #pragma unroll
        for (int c = 0; c < 4; c++)
            s = fmaf(Wr[g * 4 + c], r[(g * 4 + c) * 49 + tid], s);
        ros[tid] = s;
    }
    __syncthreads();

    const float wq = Wq[g], wk = Wk[g], wvw = Wv[g];
    const float u  = up[g], v  = vp[g];

    const int lw = tid % WW;             // column 0..55
    const int rg = tid / WW;             // row-group 0..3, 7 rows each
    const float* base = sp + rg * 7 * PW + lw;
    float* outp = out + (size_t)plane * HH * WW + (size_t)(h0 + rg * 7) * WW + lw;

    // ---------- Pass A: pixels 0..3 (window rows 0..9) ----------
    {
        float q0 = base[3 * PW + 3] * wq;
        float q1 = base[4 * PW + 3] * wq;
        float q2 = base[5 * PW + 3] * wq;
        float q3 = base[6 * PW + 3] * wq;
        u64 a01 = pack2((q0 + u) * wk * LOG2E, (q1 + u) * wk * LOG2E);
        u64 a23 = pack2((q2 + u) * wk * LOG2E, (q3 + u) * wk * LOG2E);
        u64 b01 = pack2((q0 + v) * LOG2E, (q1 + v) * LOG2E);
        u64 b23 = pack2((q2 + v) * LOG2E, (q3 + v) * LOG2E);

        u64 s01 = 0, A01 = 0, s23 = 0, A23 = 0;
        #pragma unroll
        for (int j = 0; j < KW; j++) {
            float wa[10];
            #pragma unroll
            for (int rr = 0; rr < 10; rr++) wa[rr] = base[rr * PW + j];
            #pragma unroll
            for (int i = 0; i < KW; i++) {
                float rt = ros[i * KW + j];
                u64 rod = pack2(rt, rt);
                u64 w01 = pack2(wa[i],     wa[i + 1]);
                u64 w23 = pack2(wa[i + 2], wa[i + 3]);
                u64 l01 = fma2(a01, w01, mul2(b01, rod));
                u64 l23 = fma2(a23, w23, mul2(b23, rod));
                float x0, x1, x2, x3;
                unpack2(x0, x1, l01);
                unpack2(x2, x3, l23);
                u64 p01 = pack2(ex2a(x0), ex2a(x1));
                u64 p23 = pack2(ex2a(x2), ex2a(x3));
                s01 = add2(s01, p01); A01 = fma2(p01, w01, A01);
                s23 = add2(s23, p23); A23 = fma2(p23, w23, A23);
            }
        }
        float sa, sb, aa, ab;
        unpack2(sa, sb, s01); unpack2(aa, ab, A01);
        outp[0 * WW] = aa * wvw * rcpa(sa);
        outp[1 * WW] = ab * wvw * rcpa(sb);
        unpack2(sa, sb, s23); unpack2(aa, ab, A23);
        outp[2 * WW] = aa * wvw * rcpa(sa);
        outp[3 * WW] = ab * wvw * rcpa(sb);
    }

    // ---------- Pass B: pixels 4..6 (window rows 4..12) ----------
    {
        float q4 = base[7 * PW + 3] * wq;
        float q5 = base[8 * PW + 3] * wq;
        float q6 = base[9 * PW + 3] * wq;
        u64 a45 = pack2((q4 + u) * wk * LOG2E, (q5 + u) * wk * LOG2E);
        u64 b45 = pack2((q4 + v) * LOG2E, (q5 + v) * LOG2E);
        float a6 = (q6 + u) * wk * LOG2E;
        float b6 = (q6 + v) * LOG2E;

        u64 s45 = 0, A45 = 0;
        float s6 = 0.0f, A6 = 0.0f;
        #pragma unroll
        for (int j = 0; j < KW; j++) {
            float wb[9];
            #pragma unroll
            for (int rr = 0; rr < 9; rr++) wb[rr] = base[(rr + 4) * PW + j];
            #pragma unroll
            for (int i = 0; i < KW; i++) {
                float rt = ros[i * KW + j];
                u64 rod = pack2(rt, rt);
                u64 w45 = pack2(wb[i], wb[i + 1]);
                u64 l45 = fma2(a45, w45, mul2(b45, rod));
                float x4, x5;
                unpack2(x4, x5, l45);
                u64 p45 = pack2(ex2a(x4), ex2a(x5));
                s45 = add2(s45, p45); A45 = fma2(p45, w45, A45);

                float w6 = wb[i + 2];
                float p6 = ex2a(fmaf(a6, w6, b6 * rt));
                s6 += p6; A6 = fmaf(p6, w6, A6);
            }
        }
        float sa, sb, aa, ab;
        unpack2(sa, sb, s45); unpack2(aa, ab, A45);
        outp[4 * WW] = aa * wvw * rcpa(sa);
        outp[5 * WW] = ab * wvw * rcpa(sb);
        outp[6 * WW] = A6 * wvw * rcpa(s6);
    }
}

extern "C" void kernel_launch(void* const* d_in, const int* in_sizes, int n_in,
                              void* d_out, int out_size)
{
    const float* x  = (const float*)d_in[0];
    const float* r  = (const float*)d_in[1];
    const float* Wq = (const float*)d_in[2];
    const float* Wk = (const float*)d_in[3];
    const float* Wv = (const float*)d_in[4];
    const float* Wr = (const float*)d_in[5];
    const float* up = (const float*)d_in[6];
    const float* vp = (const float*)d_in[7];
    float* out = (float*)d_out;

    dim3 grid(HH / TH, 4 * 64);   // (2 row-tiles, 256 planes) = 512 blocks, single wave
    saconv_kernel<<<grid, NT>>>(x, r, Wq, Wk, Wv, Wr, up, vp, out);
}

// round 10
// speedup vs baseline: 1.4138x; 1.4138x over previous
#include <cuda_runtime.h>
#include <cuda_bf16.h>

// SAConv: B=4, C=G=COUT=64, D=1, H=W=56, K=7, PAD=3, RDIM=256.
//   q = x*wq; logit_t = (q+u)*wk*xw_t + (q+v)*ro_t,  ro_t = sum_c Wr[g,c]*r[g*4+c,t]
//   out = wv * sum_t softmax(logit)_t * xw_t   (no max-subtraction; |logit| small)
// Two horizontally adjacent pixels per thread: window rows are 8 contiguous smem
// floats (LDS.64 x4), ro shared via duplicated-float2 broadcast, f32x2 packed math.

#define KW    7
#define PADX  3
#define HH    56
#define WW    56
#define TH    8           // output rows per block tile -> grid = 7 x 256 = 1792
#define PW    62          // padded width 56+6
#define SROWS (TH + 6)    // 14 padded rows staged
#define NT    224         // 28 col-pairs x 8 rows; 2 adjacent pixels per thread
#define LOG2E 1.4426950408889634f

typedef unsigned long long u64;

__device__ __forceinline__ float ex2a(float x) {
    float y; asm("ex2.approx.ftz.f32 %0, %1;" : "=f"(y) : "f"(x)); return y;
}
__device__ __forceinline__ float rcpa(float x) {
    float y; asm("rcp.approx.ftz.f32 %0, %1;" : "=f"(y) : "f"(x)); return y;
}
__device__ __forceinline__ u64 pack2(float lo, float hi) {
    u64 r; asm("mov.b64 %0, {%1, %2};" : "=l"(r) : "f"(lo), "f"(hi)); return r;
}
__device__ __forceinline__ void unpack2(float& lo, float& hi, u64 v) {
    asm("mov.b64 {%0, %1}, %2;" : "=f"(lo), "=f"(hi) : "l"(v));
}
__device__ __forceinline__ u64 mul2(u64 a, u64 b) {
    u64 r; asm("mul.rn.f32x2 %0, %1, %2;" : "=l"(r) : "l"(a), "l"(b)); return r;
}
__device__ __forceinline__ u64 add2(u64 a, u64 b) {
    u64 r; asm("add.rn.f32x2 %0, %1, %2;" : "=l"(r) : "l"(a), "l"(b)); return r;
}
__device__ __forceinline__ u64 fma2(u64 a, u64 b, u64 c) {
    u64 r; asm("fma.rn.f32x2 %0, %1, %2, %3;" : "=l"(r) : "l"(a), "l"(b), "l"(c)); return r;
}

__global__ __launch_bounds__(NT, 5)
void saconv_kernel(const float* __restrict__ x,  const float* __restrict__ r,
                   const float* __restrict__ Wq, const float* __restrict__ Wk,
                   const float* __restrict__ Wv, const float* __restrict__ Wr,
                   const float* __restrict__ up, const float* __restrict__ vp,
                   float* __restrict__ out)
{
    __shared__ float sp[SROWS * PW];
    __shared__ float2 ro2[49];          // ro_t duplicated in both lanes

    const int tile  = blockIdx.x;        // 0..6 (row tiles)
    const int plane = blockIdx.y;        // 0..255 = b*64 + g
    const int g     = plane & 63;
    const int tid   = threadIdx.x;
    const int h0    = tile * TH;

    // Stage padded plane slice: padded rows [h0, h0+SROWS).
    const float* xp = x + (size_t)plane * HH * WW;
    #pragma unroll
    for (int k = 0; k < (SROWS * PW + NT - 1) / NT; k++) {
        int idx = tid + k * NT;
        if (idx < SROWS * PW) {
            int pr = idx / PW, pc = idx - pr * PW;
            int gh = h0 + pr - PADX;
            int gw = pc - PADX;
            float vv = 0.0f;
            if ((unsigned)gh < HH && (unsigned)gw < WW) vv = xp[gh * WW + gw];
            sp[idx] = vv;
        }
    }

    // ro[t] = sum_c Wr[g,0,c] * r[g*4+c, t], duplicated into both float2 lanes.
    if (tid < 49) {
        float s = 0.0f;
        #pragma unroll
        for (int c = 0; c < 4; c++)
            s = fmaf(Wr[g * 4 + c], r[(g * 4 + c) * 49 + tid], s);
        ro2[tid] = make_float2(s, s);
    }
    __syncthreads();

    const float wq = Wq[g], wk = Wk[g], wvw = Wv[g];
    const float u  = up[g], v  = vp[g];

    const int cp = tid % 28;             // column pair: cols 2cp, 2cp+1
    const int rg = tid / 28;             // output row within tile: 0..7
    const float* base = sp + rg * PW + 2 * cp;   // window origin (padded)
    float* outp = out + (size_t)plane * HH * WW + (size_t)(h0 + rg) * WW + 2 * cp;

    // Per-pixel affine coefficients (log2 domain).
    float q0 = base[3 * PW + 3] * wq;
    float q1 = base[3 * PW + 4] * wq;
    u64 a01 = pack2((q0 + u) * wk * LOG2E, (q1 + u) * wk * LOG2E);
    u64 b01 = pack2((q0 + v) * LOG2E,      (q1 + v) * LOG2E);

    u64 s01 = 0, A01 = 0;
    #pragma unroll
    for (int i = 0; i < KW; i++) {
        const float2* rp = (const float2*)(base + i * PW);
        float2 ra = rp[0], rb = rp[1], rc = rp[2], rd = rp[3];
        float f0 = ra.x, f1 = ra.y, f2 = rb.x, f3 = rb.y;
        float f4 = rc.x, f5 = rc.y, f6 = rd.x, f7 = rd.y;
        float fr[8] = {f0, f1, f2, f3, f4, f5, f6, f7};
        #pragma unroll
        for (int j = 0; j < KW; j++) {
            float2 rr = ro2[i * KW + j];
            u64 rod = pack2(rr.x, rr.y);
            u64 w01 = pack2(fr[j], fr[j + 1]);
            u64 l01 = fma2(a01, w01, mul2(b01, rod));
            float l0, l1; unpack2(l0, l1, l01);
            u64 p01 = pack2(ex2a(l0), ex2a(l1));
            s01 = add2(s01, p01);
            A01 = fma2(p01, w01, A01);
        }
    }

    float sa, sb, aa, ab;
    unpack2(sa, sb, s01);
    unpack2(aa, ab, A01);
    float2 o;
    o.x = aa * wvw * rcpa(sa);
    o.y = ab * wvw * rcpa(sb);
    *(float2*)outp = o;                  // STG.64 (8B-aligned: even column)
}

extern "C" void kernel_launch(void* const* d_in, const int* in_sizes, int n_in,
                              void* d_out, int out_size)
{
    const float* x  = (const float*)d_in[0];
    const float* r  = (const float*)d_in[1];
    const float* Wq = (const float*)d_in[2];
    const float* Wk = (const float*)d_in[3];
    const float* Wv = (const float*)d_in[4];
    const float* Wr = (const float*)d_in[5];
    const float* up = (const float*)d_in[6];
    const float* vp = (const float*)d_in[7];
    float* out = (float*)d_out;

    dim3 grid(HH / TH, 4 * 64);   // (7 row-tiles, 256 planes) = 1792 blocks
    saconv_kernel<<<grid, NT>>>(x, r, Wq, Wk, Wv, Wr, up, vp, out);
}